// round 6
// baseline (speedup 1.0000x reference)
#include <cuda_runtime.h>
#include <math_constants.h>

#define NROWS 8192
#define IN_DIM 128
#define HID 256
#define SLOPE 0.01f
#define S_CONST 8192.0f

// ---------------- scratch (__device__ globals; no allocs allowed) ----------
__device__ __align__(16) float g_H[NROWS * HID];         // exp(lrelu(s*(XW^T+b)))  (8 MB)
__device__ __align__(16) float g_Ppart[32 * 128 * HID];  // [r][kb][c] split-K partials (4 MB)
__device__ __align__(16) float g_v[NROWS];               // normalized flat[:8192]
__device__ __align__(16) float g_Upart[32 * IN_DIM];     // per-v-row partials of v^T X

// ---------------- kernel A: H = exp(lrelu(s*(X@W^T + b))) ------------------
// grid 256 blocks (32 rows each), 256 threads (one output column each)
// mainloop in packed fma.rn.f32x2: 2 FFMA2 per float4 instead of 4 FFMA
__global__ void k_zh(const float* __restrict__ X, const float* __restrict__ W,
                     const float* __restrict__ b,
                     const float* __restrict__ Ai, const float* __restrict__ Aj) {
    __shared__ float4 Xs[32][32];   // 32 rows x 128 floats, [row][k4]
    __shared__ float sred[128];
    const int c  = threadIdx.x;
    const int r0 = blockIdx.x * 32;

    if (c < 128) sred[c] = Ai[c] + Aj[c];

    const float4* X4 = (const float4*)(X + (size_t)r0 * IN_DIM);
    for (int i = c; i < 32 * 32; i += 256)
        ((float4*)Xs)[i] = X4[i];
    __syncthreads();

    // finish s-reduction
    if (c < 64) sred[c] += sred[c + 64];
    __syncthreads();
    if (c < 32) {
        float x = sred[c] + sred[c + 32];
#pragma unroll
        for (int o = 16; o > 0; o >>= 1) x += __shfl_xor_sync(0xffffffffu, x, o);
        if (c == 0) sred[0] = x;
    }
    __syncthreads();
    const float s  = sred[0];
    const float bc = b[c];

    unsigned long long acc[32];
#pragma unroll
    for (int r = 0; r < 32; r++) acc[r] = 0ull;   // {0.f, 0.f}

    const ulonglong2* W8 = (const ulonglong2*)(W + (size_t)c * IN_DIM);
#pragma unroll 1
    for (int k4 = 0; k4 < 32; k4++) {
        ulonglong2 wv = W8[k4];                    // two packed f32x2 of W[c]
#pragma unroll
        for (int r = 0; r < 32; r++) {
            ulonglong2 xv = *(const ulonglong2*)(&Xs[r][k4]);  // broadcast LDS.128
            asm("fma.rn.f32x2 %0, %1, %2, %0;" : "+l"(acc[r]) : "l"(xv.x), "l"(wv.x));
            asm("fma.rn.f32x2 %0, %1, %2, %0;" : "+l"(acc[r]) : "l"(xv.y), "l"(wv.y));
        }
    }

#pragma unroll
    for (int r = 0; r < 32; r++) {
        float lo, hi;
        asm("mov.b64 {%0, %1}, %2;" : "=f"(lo), "=f"(hi) : "l"(acc[r]));
        float z  = lo + hi;
        float a  = (z + bc) * s;
        float lr = a > 0.f ? a : SLOPE * a;
        g_H[(size_t)(r0 + r) * HID + c] = __expf(lr);
    }
}

// ---------------- kernel B: split-K partials of P = E[0:32,:] @ H ----------
// grid 128 blocks; block kb handles k in [kb*64, kb*64+64)
__global__ void k_ep(const float* __restrict__ E) {
    __shared__ __align__(16) float Es[64][32];   // [kk][r]: broadcast float4 reads
    const int c  = threadIdx.x;
    const int kb = blockIdx.x;
    const int k0 = kb * 64;

    for (int i = c; i < 64 * 32; i += 256) {
        int r = i & 31, kk = i >> 5;
        Es[kk][r] = E[(size_t)r * NROWS + k0 + kk];
    }
    __syncthreads();

    float acc[32];
#pragma unroll
    for (int r = 0; r < 32; r++) acc[r] = 0.f;

#pragma unroll 4
    for (int kk = 0; kk < 64; kk++) {
        float h = g_H[(size_t)(k0 + kk) * HID + c];
        const float4* es4 = (const float4*)Es[kk];
#pragma unroll
        for (int r4 = 0; r4 < 8; r4++) {
            float4 e = es4[r4];
            acc[r4 * 4 + 0] += e.x * h;
            acc[r4 * 4 + 1] += e.y * h;
            acc[r4 * 4 + 2] += e.z * h;
            acc[r4 * 4 + 3] += e.w * h;
        }
    }
#pragma unroll
    for (int r = 0; r < 32; r++)
        g_Ppart[((size_t)r * 128 + kb) * HID + c] = acc[r];
}

// ---------------- kernel C: reduce partials -> v; also partial of v^T X ----
// grid 32 blocks (one v-row each), 1024 threads
__global__ void k_v(const float* __restrict__ X) {
    __shared__ float sm[16][256];
    __shared__ float red[256];
    __shared__ float vsm[256];
    __shared__ float su[8][128];
    const int t = threadIdx.x;
    const int r = blockIdx.x;

    {   // phase 1: sum 128 kb-partials (contiguous, float4)
        const float4* P4 = (const float4*)(g_Ppart + (size_t)r * 128 * HID);
        const int c4 = t & 63, y = t >> 6;
        float4 a = make_float4(0.f, 0.f, 0.f, 0.f);
#pragma unroll
        for (int m = 0; m < 8; m++) {
            float4 p = P4[(size_t)(y + 16 * m) * 64 + c4];
            a.x += p.x; a.y += p.y; a.z += p.z; a.w += p.w;
        }
        sm[y][c4 * 4 + 0] = a.x;
        sm[y][c4 * 4 + 1] = a.y;
        sm[y][c4 * 4 + 2] = a.z;
        sm[y][c4 * 4 + 3] = a.w;
    }
    __syncthreads();

    float p = 0.f;
    if (t < 256) {
#pragma unroll
        for (int y = 0; y < 16; y++) p += sm[y][t];
        red[t] = p;
    }
    __syncthreads();
    if (t < 128) red[t] += red[t + 128];
    __syncthreads();
    if (t < 64)  red[t] += red[t + 64];
    __syncthreads();
    if (t < 32) {
        float x = red[t] + red[t + 32];
#pragma unroll
        for (int o = 16; o > 0; o >>= 1) x += __shfl_xor_sync(0xffffffffu, x, o);
        if (t == 0) red[0] = x;
    }
    __syncthreads();
    const float inv = 1.0f / red[0];
    if (t < 256) {
        float v = p * inv;
        vsm[t] = v;
        g_v[r * HID + t] = v;
    }
    __syncthreads();

    {   // phase 2: partial t_r[k] = sum_{c<256} v_c * X[256r + c][k]
        const int k = t & 127, jg = t >> 7;     // jg in [0,8)
        float acc = 0.f;
        const float* Xr = X + ((size_t)r * 256 + jg * 32) * IN_DIM + k;
#pragma unroll
        for (int jj = 0; jj < 32; jj++)
            acc += vsm[jg * 32 + jj] * Xr[(size_t)jj * IN_DIM];
        su[jg][k] = acc;
    }
    __syncthreads();
    if (t < 128) {
        float tot = 0.f;
#pragma unroll
        for (int g = 0; g < 8; g++) tot += su[g][t];
        g_Upart[r * IN_DIM + t] = tot;
    }
}

// ---------------- kernel D: redundant w + out softmax (128 rows/block) -----
// grid 64 blocks, 256 threads; each block recomputes w = ((v^T X) W^T)/S
// from g_Upart (cheap, L2-cached), then warp-per-row softmax for 16 rows/warp
__global__ void k_out(const float* __restrict__ W, const float* __restrict__ b,
                      float* __restrict__ out) {
    __shared__ __align__(16) float ts[128];
    __shared__ float ws[256];
    const int t = threadIdx.x;

    if (t < 128) {
        float a = 0.f;
#pragma unroll
        for (int rr = 0; rr < 32; rr++) a += g_Upart[rr * IN_DIM + t];
        ts[t] = a;
    }
    __syncthreads();

    {   // w[t] = dot(ts, W[t,:]) / S
        const float4* Wr = (const float4*)(W + (size_t)t * IN_DIM);
        const float4* t4 = (const float4*)ts;
        float d = 0.f;
#pragma unroll
        for (int i = 0; i < 32; i++) {
            float4 wv = Wr[i], tv = t4[i];
            d += wv.x * tv.x + wv.y * tv.y + wv.z * tv.z + wv.w * tv.w;
        }
        ws[t] = d * (1.0f / S_CONST);
    }
    __syncthreads();

    const int lane = t & 31, wid = t >> 5;
    const int rbase = blockIdx.x * 128 + wid * 16;

    float wl[8], bl[8];
#pragma unroll
    for (int q = 0; q < 8; q++) {
        wl[q] = ws[lane + 32 * q];
        bl[q] = b[lane + 32 * q];
    }

    for (int rr = 0; rr < 16; rr++) {
        const int i = rbase + rr;
        const float vi = g_v[i];
        float l[8];
        float m = -CUDART_INF_F;
#pragma unroll
        for (int q = 0; q < 8; q++) {
            l[q] = vi * wl[q] + bl[q];
            m = fmaxf(m, l[q]);
        }
#pragma unroll
        for (int o = 16; o > 0; o >>= 1) m = fmaxf(m, __shfl_xor_sync(0xffffffffu, m, o));
        float sum = 0.f;
#pragma unroll
        for (int q = 0; q < 8; q++) { l[q] = __expf(l[q] - m); sum += l[q]; }
#pragma unroll
        for (int o = 16; o > 0; o >>= 1) sum += __shfl_xor_sync(0xffffffffu, sum, o);
        const float inv = 1.0f / sum;
#pragma unroll
        for (int q = 0; q < 8; q++)
            out[(size_t)i * HID + lane + 32 * q] = l[q] * inv;
    }
}

// ---------------- kernel E: alpha = outer(v,v)/S, 16 rows/block, pure store
__global__ void __launch_bounds__(512) k_alpha(float* __restrict__ alpha) {
    const int t  = threadIdx.x;
    const int i0 = blockIdx.x * 16;

    float a[16];
#pragma unroll
    for (int r = 0; r < 16; r++)
        a[r] = g_v[i0 + r] * (1.0f / S_CONST);

    const float4* v4 = (const float4*)g_v;
#pragma unroll
    for (int it = 0; it < 4; it++) {
        const int c = t + 512 * it;
        float4 vv = v4[c];
#pragma unroll
        for (int r = 0; r < 16; r++) {
            float4* o4 = (float4*)(alpha + (size_t)(i0 + r) * NROWS);
            o4[c] = make_float4(a[r] * vv.x, a[r] * vv.y, a[r] * vv.z, a[r] * vv.w);
        }
    }
}

// ---------------- launch ---------------------------------------------------
extern "C" void kernel_launch(void* const* d_in, const int* in_sizes, int n_in,
                              void* d_out, int out_size) {
    const float* X  = (const float*)d_in[0];
    const float* E  = (const float*)d_in[1];
    const float* W  = (const float*)d_in[2];
    const float* b  = (const float*)d_in[3];
    const float* Ai = (const float*)d_in[4];
    const float* Aj = (const float*)d_in[5];

    float* out   = (float*)d_out;                       // (8192, 256)
    float* alpha = out + (size_t)NROWS * HID;           // (8192, 8192)

    k_zh   <<<256, 256>>>(X, W, b, Ai, Aj);
    k_ep   <<<128, 256>>>(E);
    k_v    <<<32, 1024>>>(X);
    k_out  <<<64, 256>>>(W, b, out);
    k_alpha<<<512, 512>>>(alpha);
}

// round 7
// speedup vs baseline: 1.2028x; 1.2028x over previous
#include <cuda_runtime.h>
#include <math_constants.h>

#define NROWS 8192
#define IN_DIM 128
#define HID 256
#define SLOPE 0.01f
#define S_CONST 8192.0f

// ---------------- scratch (__device__ globals; no allocs allowed) ----------
__device__ __align__(16) float g_H[NROWS * HID];         // exp(lrelu(s*(XW^T+b)))  (8 MB)
__device__ __align__(16) float g_Ppart[32 * 128 * HID];  // [r][kb][c] split-K partials (4 MB)
__device__ __align__(16) float g_v[NROWS];               // normalized flat[:8192]
__device__ __align__(16) float g_Upart[32 * IN_DIM];     // per-v-row partials of v^T X

// ---------------- kernel A: H = exp(lrelu(s*(X@W^T + b))) ------------------
// grid 128 blocks (64 rows each), 256 threads (one output column each)
__global__ void k_zh(const float* __restrict__ X, const float* __restrict__ W,
                     const float* __restrict__ b,
                     const float* __restrict__ Ai, const float* __restrict__ Aj) {
    __shared__ float4 Xs[64][32];   // 64 rows x 128 floats, [row][k4]
    __shared__ float sred[128];
    const int c  = threadIdx.x;
    const int r0 = blockIdx.x * 64;

    if (c < 128) sred[c] = Ai[c] + Aj[c];

    const float4* X4 = (const float4*)(X + (size_t)r0 * IN_DIM);
    for (int i = c; i < 64 * 32; i += 256)
        ((float4*)Xs)[i] = X4[i];
    __syncthreads();

    // finish s-reduction
    if (c < 64) sred[c] += sred[c + 64];
    __syncthreads();
    if (c < 32) {
        float x = sred[c] + sred[c + 32];
#pragma unroll
        for (int o = 16; o > 0; o >>= 1) x += __shfl_xor_sync(0xffffffffu, x, o);
        if (c == 0) sred[0] = x;
    }
    __syncthreads();
    const float s  = sred[0];
    const float bc = b[c];

    float acc[64];
#pragma unroll
    for (int r = 0; r < 64; r++) acc[r] = 0.f;

    const float4* W4 = (const float4*)(W + (size_t)c * IN_DIM);
#pragma unroll 1
    for (int k4 = 0; k4 < 32; k4++) {
        float4 wv = W4[k4];
#pragma unroll
        for (int r = 0; r < 64; r++) {
            float4 xv = Xs[r][k4];                        // broadcast LDS.128
            acc[r] += xv.x * wv.x + xv.y * wv.y + xv.z * wv.z + xv.w * wv.w;
        }
    }

#pragma unroll
    for (int r = 0; r < 64; r++) {
        float a  = (acc[r] + bc) * s;
        float lr = a > 0.f ? a : SLOPE * a;
        g_H[(size_t)(r0 + r) * HID + c] = __expf(lr);
    }
}

// ---------------- kernel B: split-K partials of P = E[0:32,:] @ H ----------
// grid 128 blocks; block kb handles k in [kb*64, kb*64+64)
__global__ void k_ep(const float* __restrict__ E) {
    __shared__ __align__(16) float Es[64][32];   // [kk][r]: broadcast float4 reads
    const int c  = threadIdx.x;
    const int kb = blockIdx.x;
    const int k0 = kb * 64;

    for (int i = c; i < 64 * 32; i += 256) {
        int r = i & 31, kk = i >> 5;
        Es[kk][r] = E[(size_t)r * NROWS + k0 + kk];
    }
    __syncthreads();

    float acc[32];
#pragma unroll
    for (int r = 0; r < 32; r++) acc[r] = 0.f;

#pragma unroll 4
    for (int kk = 0; kk < 64; kk++) {
        float h = g_H[(size_t)(k0 + kk) * HID + c];
        const float4* es4 = (const float4*)Es[kk];
#pragma unroll
        for (int r4 = 0; r4 < 8; r4++) {
            float4 e = es4[r4];
            acc[r4 * 4 + 0] += e.x * h;
            acc[r4 * 4 + 1] += e.y * h;
            acc[r4 * 4 + 2] += e.z * h;
            acc[r4 * 4 + 3] += e.w * h;
        }
    }
#pragma unroll
    for (int r = 0; r < 32; r++)
        g_Ppart[((size_t)r * 128 + kb) * HID + c] = acc[r];
}

// ---------------- kernel C: reduce partials -> v; also partial of v^T X ----
// grid 32 blocks (one v-row each), 1024 threads
__global__ void k_v(const float* __restrict__ X) {
    __shared__ float sm[16][256];
    __shared__ float red[256];
    __shared__ float vsm[256];
    __shared__ float su[8][128];
    const int t = threadIdx.x;
    const int r = blockIdx.x;

    {   // phase 1: sum 128 kb-partials (contiguous, float4)
        const float4* P4 = (const float4*)(g_Ppart + (size_t)r * 128 * HID);
        const int c4 = t & 63, y = t >> 6;
        float4 a = make_float4(0.f, 0.f, 0.f, 0.f);
#pragma unroll
        for (int m = 0; m < 8; m++) {
            float4 p = P4[(size_t)(y + 16 * m) * 64 + c4];
            a.x += p.x; a.y += p.y; a.z += p.z; a.w += p.w;
        }
        sm[y][c4 * 4 + 0] = a.x;
        sm[y][c4 * 4 + 1] = a.y;
        sm[y][c4 * 4 + 2] = a.z;
        sm[y][c4 * 4 + 3] = a.w;
    }
    __syncthreads();

    float p = 0.f;
    if (t < 256) {
#pragma unroll
        for (int y = 0; y < 16; y++) p += sm[y][t];
        red[t] = p;
    }
    __syncthreads();
    if (t < 128) red[t] += red[t + 128];
    __syncthreads();
    if (t < 64)  red[t] += red[t + 64];
    __syncthreads();
    if (t < 32) {
        float x = red[t] + red[t + 32];
#pragma unroll
        for (int o = 16; o > 0; o >>= 1) x += __shfl_xor_sync(0xffffffffu, x, o);
        if (t == 0) red[0] = x;
    }
    __syncthreads();
    const float inv = 1.0f / red[0];
    if (t < 256) {
        float v = p * inv;
        vsm[t] = v;
        g_v[r * HID + t] = v;
    }
    __syncthreads();

    {   // phase 2: partial t_r[k] = sum_{c<256} v_c * X[256r + c][k]
        const int k = t & 127, jg = t >> 7;     // jg in [0,8)
        float acc = 0.f;
        const float* Xr = X + ((size_t)r * 256 + jg * 32) * IN_DIM + k;
#pragma unroll
        for (int jj = 0; jj < 32; jj++)
            acc += vsm[jg * 32 + jj] * Xr[(size_t)jj * IN_DIM];
        su[jg][k] = acc;
    }
    __syncthreads();
    if (t < 128) {
        float tot = 0.f;
#pragma unroll
        for (int g = 0; g < 8; g++) tot += su[g][t];
        g_Upart[r * IN_DIM + t] = tot;
    }
}

// ---------------- kernel D (fused): out blocks + alpha blocks --------------
// grid = 64 + 8192, 256 threads.
//   bid < 64   : redundant-w + softmax for 128 rows (hides under alpha's DRAM wall)
//   bid >= 64  : alpha[bid-64,:] = (v_i/S) * v  (R2's proven 1-row store block)
__global__ void k_final(const float* __restrict__ W, const float* __restrict__ b,
                        float* __restrict__ out, float* __restrict__ alpha) {
    const int t = threadIdx.x;

    if (blockIdx.x < 64) {
        // ---- out path: recompute w from g_Upart (L2-cached), then softmax ----
        __shared__ __align__(16) float ts[128];
        __shared__ float ws[256];

        if (t < 128) {
            float a = 0.f;
#pragma unroll
            for (int rr = 0; rr < 32; rr++) a += g_Upart[rr * IN_DIM + t];
            ts[t] = a;
        }
        __syncthreads();

        {   // w[t] = dot(ts, W[t,:]) / S
            const float4* Wr = (const float4*)(W + (size_t)t * IN_DIM);
            const float4* t4 = (const float4*)ts;
            float d = 0.f;
#pragma unroll
            for (int i = 0; i < 32; i++) {
                float4 wv = Wr[i], tv = t4[i];
                d += wv.x * tv.x + wv.y * tv.y + wv.z * tv.z + wv.w * tv.w;
            }
            ws[t] = d * (1.0f / S_CONST);
        }
        __syncthreads();

        const int lane = t & 31, wid = t >> 5;
        const int rbase = blockIdx.x * 128 + wid * 16;

        float wl[8], bl[8];
#pragma unroll
        for (int q = 0; q < 8; q++) {
            wl[q] = ws[lane + 32 * q];
            bl[q] = b[lane + 32 * q];
        }

        for (int rr = 0; rr < 16; rr++) {
            const int i = rbase + rr;
            const float vi = g_v[i];
            float l[8];
            float m = -CUDART_INF_F;
#pragma unroll
            for (int q = 0; q < 8; q++) {
                l[q] = vi * wl[q] + bl[q];
                m = fmaxf(m, l[q]);
            }
#pragma unroll
            for (int o = 16; o > 0; o >>= 1) m = fmaxf(m, __shfl_xor_sync(0xffffffffu, m, o));
            float sum = 0.f;
#pragma unroll
            for (int q = 0; q < 8; q++) { l[q] = __expf(l[q] - m); sum += l[q]; }
#pragma unroll
            for (int o = 16; o > 0; o >>= 1) sum += __shfl_xor_sync(0xffffffffu, sum, o);
            const float inv = 1.0f / sum;
#pragma unroll
            for (int q = 0; q < 8; q++)
                out[(size_t)i * HID + lane + 32 * q] = l[q] * inv;
        }
    } else {
        // ---- alpha path: one row per block (R2's measured-best store block) ----
        const int i = blockIdx.x - 64;
        const float a = g_v[i] * (1.0f / S_CONST);
        const float4* v4 = (const float4*)g_v;
        float4* o4 = (float4*)(alpha + (size_t)i * NROWS);
#pragma unroll
        for (int it = 0; it < 8; it++) {
            float4 vv = v4[t + 256 * it];
            o4[t + 256 * it] = make_float4(a * vv.x, a * vv.y, a * vv.z, a * vv.w);
        }
    }
}

// ---------------- launch ---------------------------------------------------
extern "C" void kernel_launch(void* const* d_in, const int* in_sizes, int n_in,
                              void* d_out, int out_size) {
    const float* X  = (const float*)d_in[0];
    const float* E  = (const float*)d_in[1];
    const float* W  = (const float*)d_in[2];
    const float* b  = (const float*)d_in[3];
    const float* Ai = (const float*)d_in[4];
    const float* Aj = (const float*)d_in[5];

    float* out   = (float*)d_out;                       // (8192, 256)
    float* alpha = out + (size_t)NROWS * HID;           // (8192, 8192)

    k_zh   <<<128, 256>>>(X, W, b, Ai, Aj);
    k_ep   <<<128, 256>>>(E);
    k_v    <<<32, 1024>>>(X);
    k_final<<<64 + NROWS, 256>>>(W, b, out, alpha);
}

// round 8
// speedup vs baseline: 1.2669x; 1.0533x over previous
#include <cuda_runtime.h>
#include <math_constants.h>

#define NROWS 8192
#define IN_DIM 128
#define HID 256
#define SLOPE 0.01f
#define S_CONST 8192.0f

// ---------------- scratch (__device__ globals; no allocs allowed) ----------
__device__ __align__(16) float g_Ppart[32 * 256 * HID];  // [r][kb][c] split-K partials (8 MB)
__device__ __align__(16) float g_v[NROWS];               // normalized flat[:8192]
__device__ __align__(16) float g_Upart[32 * IN_DIM];     // per-v-row partials of v^T X

// ---------------- kernel A (fused): H-rows in registers -> Ep partials -----
// grid 256 blocks (32 rows each), 256 threads (one H-column each).
// Block bid: computes h[r] = exp(lrelu(s*(X[r0+r]·W[c] + b[c]))) for its 32
// rows entirely in registers, then the Ep partial for k-chunk [r0, r0+32):
//   Ppart[r][bid][c] = sum_kk E[r][r0+kk] * h[kk]
// H never touches memory.
__global__ void k_zhe(const float* __restrict__ X, const float* __restrict__ W,
                      const float* __restrict__ b, const float* __restrict__ E,
                      const float* __restrict__ Ai, const float* __restrict__ Aj) {
    __shared__ float4 Xs[32][32];                // 32 rows x 128 floats
    __shared__ __align__(16) float Es[32][32];   // [kk][r]: broadcast float4 reads
    __shared__ float sred[128];
    const int c  = threadIdx.x;
    const int r0 = blockIdx.x * 32;              // both H-row base and k-chunk base

    if (c < 128) sred[c] = Ai[c] + Aj[c];

    const float4* X4 = (const float4*)(X + (size_t)r0 * IN_DIM);
    for (int i = c; i < 32 * 32; i += 256)
        ((float4*)Xs)[i] = X4[i];

    // E tile: rows 0..31, cols r0..r0+31  (consecutive threads -> consecutive r:
    // conflict-free smem writes; global is a 32-row gather but only 4KB/block)
    for (int i = c; i < 32 * 32; i += 256) {
        int r = i & 31, kk = i >> 5;
        Es[kk][r] = E[(size_t)r * NROWS + r0 + kk];
    }
    __syncthreads();

    // finish s-reduction
    if (c < 64) sred[c] += sred[c + 64];
    __syncthreads();
    if (c < 32) {
        float x = sred[c] + sred[c + 32];
#pragma unroll
        for (int o = 16; o > 0; o >>= 1) x += __shfl_xor_sync(0xffffffffu, x, o);
        if (c == 0) sred[0] = x;
    }
    __syncthreads();
    const float s  = sred[0];
    const float bc = b[c];

    // ---- GEMM: acc[r] = X[r0+r,:] . W[c,:] ----
    float acc[32];
#pragma unroll
    for (int r = 0; r < 32; r++) acc[r] = 0.f;

    const float4* W4 = (const float4*)(W + (size_t)c * IN_DIM);
#pragma unroll 1
    for (int k4 = 0; k4 < 32; k4++) {
        float4 wv = W4[k4];
#pragma unroll
        for (int r = 0; r < 32; r++) {
            float4 xv = Xs[r][k4];                        // broadcast LDS.128
            acc[r] += xv.x * wv.x + xv.y * wv.y + xv.z * wv.z + xv.w * wv.w;
        }
    }

    // ---- activation in registers: acc[r] becomes H[r0+r][c] ----
#pragma unroll
    for (int r = 0; r < 32; r++) {
        float a  = (acc[r] + bc) * s;
        float lr = a > 0.f ? a : SLOPE * a;
        acc[r] = __expf(lr);
    }

    // ---- Ep partial: acc2[r] = sum_kk Es[kk][r] * acc[kk] ----
    float acc2[32];
#pragma unroll
    for (int r = 0; r < 32; r++) acc2[r] = 0.f;

#pragma unroll 4
    for (int kk = 0; kk < 32; kk++) {
        float h = acc[kk];
        const float4* es4 = (const float4*)Es[kk];
#pragma unroll
        for (int r4 = 0; r4 < 8; r4++) {
            float4 e = es4[r4];
            acc2[r4 * 4 + 0] += e.x * h;
            acc2[r4 * 4 + 1] += e.y * h;
            acc2[r4 * 4 + 2] += e.z * h;
            acc2[r4 * 4 + 3] += e.w * h;
        }
    }
#pragma unroll
    for (int r = 0; r < 32; r++)
        g_Ppart[((size_t)r * 256 + blockIdx.x) * HID + c] = acc2[r];
}

// ---------------- kernel B: reduce partials -> v; also partial of v^T X ----
// grid 32 blocks (one v-row each), 1024 threads
__global__ void k_v(const float* __restrict__ X) {
    __shared__ float sm[16][256];
    __shared__ float red[256];
    __shared__ float vsm[256];
    __shared__ float su[8][128];
    const int t = threadIdx.x;
    const int r = blockIdx.x;

    {   // phase 1: sum 256 kb-partials (contiguous, float4)
        const float4* P4 = (const float4*)(g_Ppart + (size_t)r * 256 * HID);
        const int c4 = t & 63, y = t >> 6;
        float4 a = make_float4(0.f, 0.f, 0.f, 0.f);
#pragma unroll
        for (int m = 0; m < 16; m++) {
            float4 p = P4[(size_t)(y + 16 * m) * 64 + c4];
            a.x += p.x; a.y += p.y; a.z += p.z; a.w += p.w;
        }
        sm[y][c4 * 4 + 0] = a.x;
        sm[y][c4 * 4 + 1] = a.y;
        sm[y][c4 * 4 + 2] = a.z;
        sm[y][c4 * 4 + 3] = a.w;
    }
    __syncthreads();

    float p = 0.f;
    if (t < 256) {
#pragma unroll
        for (int y = 0; y < 16; y++) p += sm[y][t];
        red[t] = p;
    }
    __syncthreads();
    if (t < 128) red[t] += red[t + 128];
    __syncthreads();
    if (t < 64)  red[t] += red[t + 64];
    __syncthreads();
    if (t < 32) {
        float x = red[t] + red[t + 32];
#pragma unroll
        for (int o = 16; o > 0; o >>= 1) x += __shfl_xor_sync(0xffffffffu, x, o);
        if (t == 0) red[0] = x;
    }
    __syncthreads();
    const float inv = 1.0f / red[0];
    if (t < 256) {
        float v = p * inv;
        vsm[t] = v;
        g_v[r * HID + t] = v;
    }
    __syncthreads();

    {   // phase 2: partial t_r[k] = sum_{c<256} v_c * X[256r + c][k]
        const int k = t & 127, jg = t >> 7;     // jg in [0,8)
        float acc = 0.f;
        const float* Xr = X + ((size_t)r * 256 + jg * 32) * IN_DIM + k;
#pragma unroll
        for (int jj = 0; jj < 32; jj++)
            acc += vsm[jg * 32 + jj] * Xr[(size_t)jj * IN_DIM];
        su[jg][k] = acc;
    }
    __syncthreads();
    if (t < 128) {
        float tot = 0.f;
#pragma unroll
        for (int g = 0; g < 8; g++) tot += su[g][t];
        g_Upart[r * IN_DIM + t] = tot;
    }
}

// ---------------- kernel C (fused): out blocks + alpha blocks --------------
// grid = 64 + 8192, 256 threads.
//   bid < 64   : redundant-w + softmax for 128 rows (hides under alpha's DRAM wall)
//   bid >= 64  : alpha[bid-64,:] = (v_i/S) * v
__global__ void k_final(const float* __restrict__ W, const float* __restrict__ b,
                        float* __restrict__ out, float* __restrict__ alpha) {
    const int t = threadIdx.x;

    if (blockIdx.x < 64) {
        // ---- out path: recompute w from g_Upart (L2-cached), then softmax ----
        __shared__ __align__(16) float ts[128];
        __shared__ float ws[256];

        if (t < 128) {
            float a = 0.f;
#pragma unroll
            for (int rr = 0; rr < 32; rr++) a += g_Upart[rr * IN_DIM + t];
            ts[t] = a;
        }
        __syncthreads();

        {   // w[t] = dot(ts, W[t,:]) / S
            const float4* Wr = (const float4*)(W + (size_t)t * IN_DIM);
            const float4* t4 = (const float4*)ts;
            float d = 0.f;
#pragma unroll
            for (int i = 0; i < 32; i++) {
                float4 wv = Wr[i], tv = t4[i];
                d += wv.x * tv.x + wv.y * tv.y + wv.z * tv.z + wv.w * tv.w;
            }
            ws[t] = d * (1.0f / S_CONST);
        }
        __syncthreads();

        const int lane = t & 31, wid = t >> 5;
        const int rbase = blockIdx.x * 128 + wid * 16;

        float wl[8], bl[8];
#pragma unroll
        for (int q = 0; q < 8; q++) {
            wl[q] = ws[lane + 32 * q];
            bl[q] = b[lane + 32 * q];
        }

        for (int rr = 0; rr < 16; rr++) {
            const int i = rbase + rr;
            const float vi = g_v[i];
            float l[8];
            float m = -CUDART_INF_F;
#pragma unroll
            for (int q = 0; q < 8; q++) {
                l[q] = vi * wl[q] + bl[q];
                m = fmaxf(m, l[q]);
            }
#pragma unroll
            for (int o = 16; o > 0; o >>= 1) m = fmaxf(m, __shfl_xor_sync(0xffffffffu, m, o));
            float sum = 0.f;
#pragma unroll
            for (int q = 0; q < 8; q++) { l[q] = __expf(l[q] - m); sum += l[q]; }
#pragma unroll
            for (int o = 16; o > 0; o >>= 1) sum += __shfl_xor_sync(0xffffffffu, sum, o);
            const float inv = 1.0f / sum;
#pragma unroll
            for (int q = 0; q < 8; q++)
                out[(size_t)i * HID + lane + 32 * q] = l[q] * inv;
        }
    } else {
        // ---- alpha path: one row per block ----
        const int i = blockIdx.x - 64;
        const float a = g_v[i] * (1.0f / S_CONST);
        const float4* v4 = (const float4*)g_v;
        float4* o4 = (float4*)(alpha + (size_t)i * NROWS);
#pragma unroll
        for (int it = 0; it < 8; it++) {
            float4 vv = v4[t + 256 * it];
            o4[t + 256 * it] = make_float4(a * vv.x, a * vv.y, a * vv.z, a * vv.w);
        }
    }
}

// ---------------- launch ---------------------------------------------------
extern "C" void kernel_launch(void* const* d_in, const int* in_sizes, int n_in,
                              void* d_out, int out_size) {
    const float* X  = (const float*)d_in[0];
    const float* E  = (const float*)d_in[1];
    const float* W  = (const float*)d_in[2];
    const float* b  = (const float*)d_in[3];
    const float* Ai = (const float*)d_in[4];
    const float* Aj = (const float*)d_in[5];

    float* out   = (float*)d_out;                       // (8192, 256)
    float* alpha = out + (size_t)NROWS * HID;           // (8192, 8192)

    k_zhe  <<<256, 256>>>(X, W, b, E, Ai, Aj);
    k_v    <<<32, 1024>>>(X);
    k_final<<<64 + NROWS, 256>>>(W, b, out, alpha);
}